// round 11
// baseline (speedup 1.0000x reference)
#include <cuda_runtime.h>
#include <cstdint>

#define TOKENS 8192
#define HIDDEN 4096
#define INTER  11008
#define KACT   3302
#define KPAD   3328   // 26 * 128

// ---------------------------------------------------------------------------
// Static device scratch. All operands pre-converted to tf32 bit patterns,
// gathered/packed K-major, pads zero-filled.
// ---------------------------------------------------------------------------
__device__ uint32_t g_xtf [(size_t)TOKENS * HIDDEN];   // x, tf32
__device__ uint32_t g_wgtf[(size_t)KPAD   * HIDDEN];   // W_gate[aidx], pad rows = 0
__device__ uint32_t g_wutf[(size_t)KPAD   * HIDDEN];   // W_up[aidx]
__device__ uint32_t g_wdtf[(size_t)HIDDEN * KPAD];     // W_down[:, aidx], pad cols = 0
__device__ uint32_t g_htf [(size_t)TOKENS * KPAD];     // h = silu(g)*u, tf32

__device__ __forceinline__ uint32_t f2tf(float f) {
    uint32_t u; asm("cvt.rna.tf32.f32 %0, %1;" : "=r"(u) : "f"(f)); return u;
}

__device__ __forceinline__ void mma8(float c[4], const uint32_t a[4], const uint32_t b[2]) {
    asm volatile(
        "mma.sync.aligned.m16n8k8.row.col.f32.tf32.tf32.f32 "
        "{%0,%1,%2,%3}, {%4,%5,%6,%7}, {%8,%9}, {%0,%1,%2,%3};\n"
        : "+f"(c[0]), "+f"(c[1]), "+f"(c[2]), "+f"(c[3])
        : "r"(a[0]), "r"(a[1]), "r"(a[2]), "r"(a[3]), "r"(b[0]), "r"(b[1]));
}

__device__ __forceinline__ void cp16(uint32_t s, const void* g) {
    asm volatile("cp.async.cg.shared.global [%0], [%1], 16;\n" :: "r"(s), "l"(g));
}
#define CP_COMMIT() asm volatile("cp.async.commit_group;\n")
#define CP_WAIT1()  asm volatile("cp.async.wait_group 1;\n")

// Per-stage smem footprint (words): 3 x (128 rows x 36 words) for gateup,
// (128 + 256) x 36 for down -> both 13824 words = 55296 B. 3 stages = 165888 B.
#define STG_W  13824
#define SMEM_B (3 * STG_W * 4)

// ---------------------------------------------------------------------------
// Prep kernels: convert + gather + pad once per call (~90-230us, HBM-bound)
// ---------------------------------------------------------------------------
__global__ __launch_bounds__(256) void k_cvt_x(const float* __restrict__ x) {
    size_t i = ((size_t)blockIdx.x * 256 + threadIdx.x) * 4;
    float4 v = *(const float4*)(x + i);
    *(uint4*)(g_xtf + i) = make_uint4(f2tf(v.x), f2tf(v.y), f2tf(v.z), f2tf(v.w));
}
__global__ __launch_bounds__(256) void k_prep_gu(
    const float* __restrict__ Wg, const float* __restrict__ Wu, const int* __restrict__ aidx)
{
    int r = blockIdx.x;
    uint32_t* dg = g_wgtf + (size_t)r * HIDDEN;
    uint32_t* du = g_wutf + (size_t)r * HIDDEN;
    if (r < KACT) {
        int src = __ldg(&aidx[r]);
        const float* sg = Wg + (size_t)src * HIDDEN;
        const float* su = Wu + (size_t)src * HIDDEN;
        for (int c = threadIdx.x * 4; c < HIDDEN; c += 1024) {
            float4 g = *(const float4*)(sg + c);
            float4 u = *(const float4*)(su + c);
            *(uint4*)(dg + c) = make_uint4(f2tf(g.x), f2tf(g.y), f2tf(g.z), f2tf(g.w));
            *(uint4*)(du + c) = make_uint4(f2tf(u.x), f2tf(u.y), f2tf(u.z), f2tf(u.w));
        }
    } else {
        for (int c = threadIdx.x * 4; c < HIDDEN; c += 1024) {
            *(uint4*)(dg + c) = make_uint4(0, 0, 0, 0);
            *(uint4*)(du + c) = make_uint4(0, 0, 0, 0);
        }
    }
}
__global__ __launch_bounds__(256) void k_prep_wd(
    const float* __restrict__ Wd, const int* __restrict__ aidx)
{
    int n = blockIdx.x;
    uint32_t* dst = g_wdtf + (size_t)n * KPAD;
    const float* src = Wd + (size_t)n * INTER;
    for (int k = threadIdx.x; k < KPAD; k += 256)
        dst[k] = (k < KACT) ? f2tf(__ldg(&src[__ldg(&aidx[k])])) : 0u;
}

// ---------------------------------------------------------------------------
// Kernel 1: fused gate+up GEMM + silu epilogue.
// CTA tile 128(M tokens) x 128(N k-act) DUAL, K step 32 over HIDDEN.
// 512 threads, 16 warps in a 4x4 grid, warp tile 32x32 (g and u share A).
// 3-stage cp.async pipeline. Stage layout (words): A@0, Bg@4608, Bu@9216.
// ---------------------------------------------------------------------------
__global__ __launch_bounds__(512, 1) void k_gateup() {
    extern __shared__ uint32_t sm[];
    const int tid = threadIdx.x;
    const uint32_t sbase = (uint32_t)__cvta_generic_to_shared(sm);

    int bid   = blockIdx.x;                     // 64 m-tiles x 26 n-tiles, GRP 8
    int group = bid / (8 * 26);
    int rem   = bid - group * (8 * 26);
    const int bm = (group * 8 + (rem & 7)) * 128;
    const int bn = (rem >> 3) * 128;

    auto load_stage = [&](int s, int kt) {
        const uint32_t base = sbase + (uint32_t)(s * STG_W) * 4;
        const int gk = kt * 32;
#pragma unroll
        for (int i = 0; i < 2; ++i) {
            int ch  = tid + 512 * i;            // 0..1023
            int row = ch >> 3, c = (ch & 7) * 4;
            uint32_t so = (uint32_t)(row * 36 + c) * 4;
            cp16(base + so,            g_xtf  + (size_t)(bm + row) * HIDDEN + gk + c);
            cp16(base + 4608*4 + so,   g_wgtf + (size_t)(bn + row) * HIDDEN + gk + c);
            cp16(base + 9216*4 + so,   g_wutf + (size_t)(bn + row) * HIDDEN + gk + c);
        }
    };

    const int warp = tid >> 5, lane = tid & 31;
    const int wm = (warp & 3) * 32;
    const int wn = (warp >> 2) * 32;
    const int lr4 = lane >> 2, lc4 = lane & 3;

    float accg[2][4][4] = {};
    float accu[2][4][4] = {};

    const int KT = HIDDEN / 32;                 // 128
    load_stage(0, 0); CP_COMMIT();
    load_stage(1, 1); CP_COMMIT();

    int cur = 0;
    for (int kt = 0; kt < KT; ++kt) {
        CP_WAIT1();
        __syncthreads();                        // stage kt ready; kt-1 compute done

        if (kt + 2 < KT) {
            int nxt = cur + 2; if (nxt >= 3) nxt -= 3;
            load_stage(nxt, kt + 2);
        }
        CP_COMMIT();

        const uint32_t* As = sm + cur * STG_W;
        const uint32_t* Bg = As + 4608;
        const uint32_t* Bu = As + 9216;
#pragma unroll
        for (int kk = 0; kk < 4; ++kk) {
            const int kb = kk * 8;
            uint32_t af[2][4];
#pragma unroll
            for (int i = 0; i < 2; ++i) {
                int r = wm + i * 16 + lr4;
                af[i][0] = As[r * 36 + kb + lc4];
                af[i][1] = As[(r + 8) * 36 + kb + lc4];
                af[i][2] = As[r * 36 + kb + lc4 + 4];
                af[i][3] = As[(r + 8) * 36 + kb + lc4 + 4];
            }
            uint32_t bg[4][2], bu[4][2];
#pragma unroll
            for (int j = 0; j < 4; ++j) {
                int n = wn + j * 8 + lr4;
                bg[j][0] = Bg[n * 36 + kb + lc4];
                bg[j][1] = Bg[n * 36 + kb + lc4 + 4];
                bu[j][0] = Bu[n * 36 + kb + lc4];
                bu[j][1] = Bu[n * 36 + kb + lc4 + 4];
            }
#pragma unroll
            for (int i = 0; i < 2; ++i)
#pragma unroll
                for (int j = 0; j < 4; ++j) {
                    mma8(accg[i][j], af[i], bg[j]);
                    mma8(accu[i][j], af[i], bu[j]);
                }
        }
        if (++cur == 3) cur = 0;
    }

    // Epilogue: h = silu(g)*u stored as tf32 bits (pad cols exactly 0 by construction)
#pragma unroll
    for (int i = 0; i < 2; ++i)
#pragma unroll
        for (int j = 0; j < 4; ++j) {
            int c0 = bn + wn + j * 8 + 2 * lc4;
#pragma unroll
            for (int half = 0; half < 2; ++half) {
                int r = bm + wm + i * 16 + lr4 + half * 8;
                float g0 = accg[i][j][half * 2], g1 = accg[i][j][half * 2 + 1];
                float u0 = accu[i][j][half * 2], u1 = accu[i][j][half * 2 + 1];
                float h0 = g0 * u0 / (1.0f + __expf(-g0));
                float h1 = g1 * u1 / (1.0f + __expf(-g1));
                *(uint2*)(g_htf + (size_t)r * KPAD + c0) = make_uint2(f2tf(h0), f2tf(h1));
            }
        }
}

// ---------------------------------------------------------------------------
// Kernel 2: out = h @ Wd_packed^T.
// CTA tile 128(M) x 256(N hidden), K step 32 over KPAD. 512 threads, 16 warps
// 4x4 grid, warp tile 32x64. 3-stage cp.async. Stage layout: A@0, B@4608.
// ---------------------------------------------------------------------------
__global__ __launch_bounds__(512, 1) void k_down(float* __restrict__ out) {
    extern __shared__ uint32_t sm[];
    const int tid = threadIdx.x;
    const uint32_t sbase = (uint32_t)__cvta_generic_to_shared(sm);

    int bid   = blockIdx.x;                     // 64 m-tiles x 16 n-tiles, GRP 8
    int group = bid / (8 * 16);
    int rem   = bid - group * (8 * 16);
    const int bm = (group * 8 + (rem & 7)) * 128;
    const int bn = (rem >> 3) * 256;

    auto load_stage = [&](int s, int kt) {
        const uint32_t base = sbase + (uint32_t)(s * STG_W) * 4;
        const int gk = kt * 32;
#pragma unroll
        for (int i = 0; i < 2; ++i) {           // A: 128 rows
            int ch  = tid + 512 * i;
            int row = ch >> 3, c = (ch & 7) * 4;
            cp16(base + (uint32_t)(row * 36 + c) * 4,
                 g_htf + (size_t)(bm + row) * KPAD + gk + c);
        }
#pragma unroll
        for (int i = 0; i < 4; ++i) {           // B: 256 rows
            int ch  = tid + 512 * i;
            int row = ch >> 3, c = (ch & 7) * 4;
            cp16(base + 4608 * 4 + (uint32_t)(row * 36 + c) * 4,
                 g_wdtf + (size_t)(bn + row) * KPAD + gk + c);
        }
    };

    const int warp = tid >> 5, lane = tid & 31;
    const int wm = (warp & 3) * 32;
    const int wn = (warp >> 2) * 64;
    const int lr4 = lane >> 2, lc4 = lane & 3;

    float acc[2][8][4] = {};

    const int KT = KPAD / 32;                   // 104
    load_stage(0, 0); CP_COMMIT();
    load_stage(1, 1); CP_COMMIT();

    int cur = 0;
    for (int kt = 0; kt < KT; ++kt) {
        CP_WAIT1();
        __syncthreads();

        if (kt + 2 < KT) {
            int nxt = cur + 2; if (nxt >= 3) nxt -= 3;
            load_stage(nxt, kt + 2);
        }
        CP_COMMIT();

        const uint32_t* As = sm + cur * STG_W;
        const uint32_t* Bs = As + 4608;
#pragma unroll
        for (int kk = 0; kk < 4; ++kk) {
            const int kb = kk * 8;
            uint32_t af[2][4];
#pragma unroll
            for (int i = 0; i < 2; ++i) {
                int r = wm + i * 16 + lr4;
                af[i][0] = As[r * 36 + kb + lc4];
                af[i][1] = As[(r + 8) * 36 + kb + lc4];
                af[i][2] = As[r * 36 + kb + lc4 + 4];
                af[i][3] = As[(r + 8) * 36 + kb + lc4 + 4];
            }
            uint32_t bf[8][2];
#pragma unroll
            for (int j = 0; j < 8; ++j) {
                int n = wn + j * 8 + lr4;
                bf[j][0] = Bs[n * 36 + kb + lc4];
                bf[j][1] = Bs[n * 36 + kb + lc4 + 4];
            }
#pragma unroll
            for (int i = 0; i < 2; ++i)
#pragma unroll
                for (int j = 0; j < 8; ++j)
                    mma8(acc[i][j], af[i], bf[j]);
        }
        if (++cur == 3) cur = 0;
    }

#pragma unroll
    for (int i = 0; i < 2; ++i)
#pragma unroll
        for (int j = 0; j < 8; ++j) {
            int c0 = bn + wn + j * 8 + 2 * lc4;
#pragma unroll
            for (int half = 0; half < 2; ++half) {
                int r = bm + wm + i * 16 + lr4 + half * 8;
                *(float2*)(out + (size_t)r * HIDDEN + c0) =
                    make_float2(acc[i][j][half * 2], acc[i][j][half * 2 + 1]);
            }
        }
}

// ---------------------------------------------------------------------------
// Inputs: x[f32 8192x4096], W_gate[f32 11008x4096], W_up[f32 11008x4096],
// W_down[f32 4096x11008], active_idx[i32 3302]. Output f32 8192x4096.
// ---------------------------------------------------------------------------
extern "C" void kernel_launch(void* const* d_in, const int* in_sizes, int n_in,
                              void* d_out, int out_size)
{
    const float* x    = (const float*)d_in[0];
    const float* Wg   = (const float*)d_in[1];
    const float* Wu   = (const float*)d_in[2];
    const float* Wd   = (const float*)d_in[3];
    const int*   aidx = (const int*)  d_in[4];
    float*       out  = (float*)d_out;

    cudaFuncSetAttribute(k_gateup, cudaFuncAttributeMaxDynamicSharedMemorySize, SMEM_B);
    cudaFuncSetAttribute(k_down,   cudaFuncAttributeMaxDynamicSharedMemorySize, SMEM_B);

    k_cvt_x  <<<(TOKENS * HIDDEN) / 1024, 256>>>(x);
    k_prep_gu<<<KPAD,   256>>>(Wg, Wu, aidx);
    k_prep_wd<<<HIDDEN, 256>>>(Wd, aidx);

    k_gateup<<<(TOKENS / 128) * (KPAD / 128),   512, SMEM_B>>>();      // 1664
    k_down  <<<(TOKENS / 128) * (HIDDEN / 256), 512, SMEM_B>>>(out);   // 1024
}

// round 12
// speedup vs baseline: 1.0417x; 1.0417x over previous
#include <cuda_runtime.h>
#include <cstdint>

#define TOKENS 8192
#define HIDDEN 4096
#define INTER  11008
#define KACT   3302
#define KPAD   3328   // 26 * 128

// ---------------------------------------------------------------------------
// Static device scratch. All operands pre-converted to tf32 bit patterns,
// gathered/packed K-major, pads zero-filled.
// ---------------------------------------------------------------------------
__device__ uint32_t g_xtf [(size_t)TOKENS * HIDDEN];   // x, tf32
__device__ uint32_t g_wgtf[(size_t)KPAD   * HIDDEN];   // W_gate[aidx], pad rows = 0
__device__ uint32_t g_wutf[(size_t)KPAD   * HIDDEN];   // W_up[aidx]
__device__ uint32_t g_wdtf[(size_t)HIDDEN * KPAD];     // W_down[:, aidx], pad cols = 0
__device__ uint32_t g_htf [(size_t)TOKENS * KPAD];     // h = silu(g)*u, tf32

__device__ __forceinline__ uint32_t f2tf(float f) {
    uint32_t u; asm("cvt.rna.tf32.f32 %0, %1;" : "=r"(u) : "f"(f)); return u;
}

__device__ __forceinline__ void mma8(float c[4], const uint32_t a[4], const uint32_t b[2]) {
    asm volatile(
        "mma.sync.aligned.m16n8k8.row.col.f32.tf32.tf32.f32 "
        "{%0,%1,%2,%3}, {%4,%5,%6,%7}, {%8,%9}, {%0,%1,%2,%3};\n"
        : "+f"(c[0]), "+f"(c[1]), "+f"(c[2]), "+f"(c[3])
        : "r"(a[0]), "r"(a[1]), "r"(a[2]), "r"(a[3]), "r"(b[0]), "r"(b[1]));
}

__device__ __forceinline__ void cp16(uint32_t s, const void* g) {
    asm volatile("cp.async.cg.shared.global [%0], [%1], 16;\n" :: "r"(s), "l"(g));
}
#define CP_COMMIT() asm volatile("cp.async.commit_group;\n")
#define CP_WAIT1()  asm volatile("cp.async.wait_group 1;\n")

// Per-stage smem (words): gateup 3 x (128x36), down (128+256) x 36 -> both 13824
#define STG_W  13824
#define SMEM_B (3 * STG_W * 4)      // 165,888 B, 3 stages

// ---------------------------------------------------------------------------
// Prep kernels: convert + gather + pad once per call (HBM-bound, ~250us total)
// ---------------------------------------------------------------------------
__global__ __launch_bounds__(256) void k_cvt_x(const float* __restrict__ x) {
    size_t i = ((size_t)blockIdx.x * 256 + threadIdx.x) * 4;
    float4 v = *(const float4*)(x + i);
    *(uint4*)(g_xtf + i) = make_uint4(f2tf(v.x), f2tf(v.y), f2tf(v.z), f2tf(v.w));
}
__global__ __launch_bounds__(256) void k_prep_gu(
    const float* __restrict__ Wg, const float* __restrict__ Wu, const int* __restrict__ aidx)
{
    int r = blockIdx.x;
    uint32_t* dg = g_wgtf + (size_t)r * HIDDEN;
    uint32_t* du = g_wutf + (size_t)r * HIDDEN;
    if (r < KACT) {
        int src = __ldg(&aidx[r]);
        const float* sg = Wg + (size_t)src * HIDDEN;
        const float* su = Wu + (size_t)src * HIDDEN;
        for (int c = threadIdx.x * 4; c < HIDDEN; c += 1024) {
            float4 g = *(const float4*)(sg + c);
            float4 u = *(const float4*)(su + c);
            *(uint4*)(dg + c) = make_uint4(f2tf(g.x), f2tf(g.y), f2tf(g.z), f2tf(g.w));
            *(uint4*)(du + c) = make_uint4(f2tf(u.x), f2tf(u.y), f2tf(u.z), f2tf(u.w));
        }
    } else {
        for (int c = threadIdx.x * 4; c < HIDDEN; c += 1024) {
            *(uint4*)(dg + c) = make_uint4(0, 0, 0, 0);
            *(uint4*)(du + c) = make_uint4(0, 0, 0, 0);
        }
    }
}
__global__ __launch_bounds__(256) void k_prep_wd(
    const float* __restrict__ Wd, const int* __restrict__ aidx)
{
    int n = blockIdx.x;
    uint32_t* dst = g_wdtf + (size_t)n * KPAD;
    const float* src = Wd + (size_t)n * INTER;
    for (int k = threadIdx.x; k < KPAD; k += 256)
        dst[k] = (k < KACT) ? f2tf(__ldg(&src[__ldg(&aidx[k])])) : 0u;
}

// ---------------------------------------------------------------------------
// Kernel 1: fused gate+up GEMM + silu epilogue.
// CTA 128(M) x 128(N) DUAL, K step 32. 256 threads, 8 warps (2x4),
// warp tile 64x32 dual. 3-stage cp.async; fragment double-buffering in kk.
// Stage layout (words): A@0, Bg@4608, Bu@9216.
// ---------------------------------------------------------------------------
__global__ __launch_bounds__(256, 1) void k_gateup() {
    extern __shared__ uint32_t sm[];
    const int tid = threadIdx.x;
    const uint32_t sbase = (uint32_t)__cvta_generic_to_shared(sm);

    int bid   = blockIdx.x;                     // 64 m-tiles x 26 n-tiles, GRP 8
    int group = bid / (8 * 26);
    int rem   = bid - group * (8 * 26);
    const int bm = (group * 8 + (rem & 7)) * 128;
    const int bn = (rem >> 3) * 128;

    auto load_stage = [&](int s, int kt) {
        const uint32_t base = sbase + (uint32_t)(s * STG_W) * 4;
        const int gk = kt * 32;
#pragma unroll
        for (int i = 0; i < 4; ++i) {
            int ch  = tid + 256 * i;            // 0..1023
            int row = ch >> 3, c = (ch & 7) * 4;
            uint32_t so = (uint32_t)(row * 36 + c) * 4;
            cp16(base + so,          g_xtf  + (size_t)(bm + row) * HIDDEN + gk + c);
            cp16(base + 4608*4 + so, g_wgtf + (size_t)(bn + row) * HIDDEN + gk + c);
            cp16(base + 9216*4 + so, g_wutf + (size_t)(bn + row) * HIDDEN + gk + c);
        }
    };

    const int warp = tid >> 5, lane = tid & 31;
    const int wm = (warp & 1) * 64;
    const int wn = (warp >> 1) * 32;
    const int lr4 = lane >> 2, lc4 = lane & 3;

    float accg[4][4][4] = {};
    float accu[4][4][4] = {};

    const int KT = HIDDEN / 32;                 // 128
    load_stage(0, 0); CP_COMMIT();
    load_stage(1, 1); CP_COMMIT();

    int cur = 0;
    for (int kt = 0; kt < KT; ++kt) {
        CP_WAIT1();
        __syncthreads();

        if (kt + 2 < KT) {
            int nxt = cur + 2; if (nxt >= 3) nxt -= 3;
            load_stage(nxt, kt + 2);
        }
        CP_COMMIT();

        const uint32_t* As = sm + cur * STG_W;
        const uint32_t* Bg = As + 4608;
        const uint32_t* Bu = As + 9216;

        uint32_t afA[4][4], bgA[4][2], buA[4][2];
        uint32_t afB[4][4], bgB[4][2], buB[4][2];

        auto ldf = [&](uint32_t af[4][4], uint32_t bg[4][2], uint32_t bu[4][2], int kb) {
#pragma unroll
            for (int i = 0; i < 4; ++i) {
                int r = wm + i * 16 + lr4;
                af[i][0] = As[r * 36 + kb + lc4];
                af[i][1] = As[(r + 8) * 36 + kb + lc4];
                af[i][2] = As[r * 36 + kb + lc4 + 4];
                af[i][3] = As[(r + 8) * 36 + kb + lc4 + 4];
            }
#pragma unroll
            for (int j = 0; j < 4; ++j) {
                int n = wn + j * 8 + lr4;
                bg[j][0] = Bg[n * 36 + kb + lc4];
                bg[j][1] = Bg[n * 36 + kb + lc4 + 4];
                bu[j][0] = Bu[n * 36 + kb + lc4];
                bu[j][1] = Bu[n * 36 + kb + lc4 + 4];
            }
        };
        auto domma = [&](uint32_t af[4][4], uint32_t bg[4][2], uint32_t bu[4][2]) {
#pragma unroll
            for (int i = 0; i < 4; ++i)
#pragma unroll
                for (int j = 0; j < 4; ++j) {
                    mma8(accg[i][j], af[i], bg[j]);
                    mma8(accu[i][j], af[i], bu[j]);
                }
        };

        // Software-pipelined kk loop: LDS for kk+1 issued before MMAs of kk.
        ldf(afA, bgA, buA, 0);
        ldf(afB, bgB, buB, 8);
        domma(afA, bgA, buA);
        ldf(afA, bgA, buA, 16);
        domma(afB, bgB, buB);
        ldf(afB, bgB, buB, 24);
        domma(afA, bgA, buA);
        domma(afB, bgB, buB);

        if (++cur == 3) cur = 0;
    }

    // Epilogue: h = silu(g)*u stored as tf32 bits (pad cols exactly 0)
#pragma unroll
    for (int i = 0; i < 4; ++i)
#pragma unroll
        for (int j = 0; j < 4; ++j) {
            int c0 = bn + wn + j * 8 + 2 * lc4;
#pragma unroll
            for (int half = 0; half < 2; ++half) {
                int r = bm + wm + i * 16 + lr4 + half * 8;
                float g0 = accg[i][j][half * 2], g1 = accg[i][j][half * 2 + 1];
                float u0 = accu[i][j][half * 2], u1 = accu[i][j][half * 2 + 1];
                float h0 = g0 * u0 / (1.0f + __expf(-g0));
                float h1 = g1 * u1 / (1.0f + __expf(-g1));
                *(uint2*)(g_htf + (size_t)r * KPAD + c0) = make_uint2(f2tf(h0), f2tf(h1));
            }
        }
}

// ---------------------------------------------------------------------------
// Kernel 2: out = h @ Wd_packed^T.
// CTA 128(M) x 256(N), K step 32 over KPAD. 256 threads, 8 warps (2x4),
// warp tile 64x64. 3-stage cp.async; fragment double-buffering.
// Stage layout (words): A@0, B@4608.
// ---------------------------------------------------------------------------
__global__ __launch_bounds__(256, 1) void k_down(float* __restrict__ out) {
    extern __shared__ uint32_t sm[];
    const int tid = threadIdx.x;
    const uint32_t sbase = (uint32_t)__cvta_generic_to_shared(sm);

    int bid   = blockIdx.x;                     // 64 m-tiles x 16 n-tiles, GRP 8
    int group = bid / (8 * 16);
    int rem   = bid - group * (8 * 16);
    const int bm = (group * 8 + (rem & 7)) * 128;
    const int bn = (rem >> 3) * 256;

    auto load_stage = [&](int s, int kt) {
        const uint32_t base = sbase + (uint32_t)(s * STG_W) * 4;
        const int gk = kt * 32;
#pragma unroll
        for (int i = 0; i < 4; ++i) {           // A: 128 rows = 1024 chunks
            int ch  = tid + 256 * i;
            int row = ch >> 3, c = (ch & 7) * 4;
            cp16(base + (uint32_t)(row * 36 + c) * 4,
                 g_htf + (size_t)(bm + row) * KPAD + gk + c);
        }
#pragma unroll
        for (int i = 0; i < 8; ++i) {           // B: 256 rows = 2048 chunks
            int ch  = tid + 256 * i;
            int row = ch >> 3, c = (ch & 7) * 4;
            cp16(base + 4608 * 4 + (uint32_t)(row * 36 + c) * 4,
                 g_wdtf + (size_t)(bn + row) * KPAD + gk + c);
        }
    };

    const int warp = tid >> 5, lane = tid & 31;
    const int wm = (warp & 1) * 64;
    const int wn = (warp >> 1) * 64;
    const int lr4 = lane >> 2, lc4 = lane & 3;

    float acc[4][8][4] = {};

    const int KT = KPAD / 32;                   // 104
    load_stage(0, 0); CP_COMMIT();
    load_stage(1, 1); CP_COMMIT();

    int cur = 0;
    for (int kt = 0; kt < KT; ++kt) {
        CP_WAIT1();
        __syncthreads();

        if (kt + 2 < KT) {
            int nxt = cur + 2; if (nxt >= 3) nxt -= 3;
            load_stage(nxt, kt + 2);
        }
        CP_COMMIT();

        const uint32_t* As = sm + cur * STG_W;
        const uint32_t* Bs = As + 4608;

        uint32_t afA[4][4], bfA[8][2];
        uint32_t afB[4][4], bfB[8][2];

        auto ldf = [&](uint32_t af[4][4], uint32_t bf[8][2], int kb) {
#pragma unroll
            for (int i = 0; i < 4; ++i) {
                int r = wm + i * 16 + lr4;
                af[i][0] = As[r * 36 + kb + lc4];
                af[i][1] = As[(r + 8) * 36 + kb + lc4];
                af[i][2] = As[r * 36 + kb + lc4 + 4];
                af[i][3] = As[(r + 8) * 36 + kb + lc4 + 4];
            }
#pragma unroll
            for (int j = 0; j < 8; ++j) {
                int n = wn + j * 8 + lr4;
                bf[j][0] = Bs[n * 36 + kb + lc4];
                bf[j][1] = Bs[n * 36 + kb + lc4 + 4];
            }
        };
        auto domma = [&](uint32_t af[4][4], uint32_t bf[8][2]) {
#pragma unroll
            for (int i = 0; i < 4; ++i)
#pragma unroll
                for (int j = 0; j < 8; ++j)
                    mma8(acc[i][j], af[i], bf[j]);
        };

        ldf(afA, bfA, 0);
        ldf(afB, bfB, 8);
        domma(afA, bfA);
        ldf(afA, bfA, 16);
        domma(afB, bfB);
        ldf(afB, bfB, 24);
        domma(afA, bfA);
        domma(afB, bfB);

        if (++cur == 3) cur = 0;
    }

#pragma unroll
    for (int i = 0; i < 4; ++i)
#pragma unroll
        for (int j = 0; j < 8; ++j) {
            int c0 = bn + wn + j * 8 + 2 * lc4;
#pragma unroll
            for (int half = 0; half < 2; ++half) {
                int r = bm + wm + i * 16 + lr4 + half * 8;
                *(float2*)(out + (size_t)r * HIDDEN + c0) =
                    make_float2(acc[i][j][half * 2], acc[i][j][half * 2 + 1]);
            }
        }
}

// ---------------------------------------------------------------------------
// Inputs: x[f32 8192x4096], W_gate[f32 11008x4096], W_up[f32 11008x4096],
// W_down[f32 4096x11008], active_idx[i32 3302]. Output f32 8192x4096.
// ---------------------------------------------------------------------------
extern "C" void kernel_launch(void* const* d_in, const int* in_sizes, int n_in,
                              void* d_out, int out_size)
{
    const float* x    = (const float*)d_in[0];
    const float* Wg   = (const float*)d_in[1];
    const float* Wu   = (const float*)d_in[2];
    const float* Wd   = (const float*)d_in[3];
    const int*   aidx = (const int*)  d_in[4];
    float*       out  = (float*)d_out;

    cudaFuncSetAttribute(k_gateup, cudaFuncAttributeMaxDynamicSharedMemorySize, SMEM_B);
    cudaFuncSetAttribute(k_down,   cudaFuncAttributeMaxDynamicSharedMemorySize, SMEM_B);

    k_cvt_x  <<<(TOKENS * HIDDEN) / 1024, 256>>>(x);
    k_prep_gu<<<KPAD,   256>>>(Wg, Wu, aidx);
    k_prep_wd<<<HIDDEN, 256>>>(Wd, aidx);

    k_gateup<<<(TOKENS / 128) * (KPAD / 128),   256, SMEM_B>>>();      // 1664
    k_down  <<<(TOKENS / 128) * (HIDDEN / 256), 256, SMEM_B>>>(out);   // 1024
}

// round 13
// speedup vs baseline: 1.0477x; 1.0058x over previous
#include <cuda_runtime.h>
#include <cstdint>

#define TOKENS 8192
#define HIDDEN 4096
#define INTER  11008
#define KACT   3302
#define KPAD   3328   // 26 * 128

// ---------------------------------------------------------------------------
// Static device scratch. All operands pre-converted to tf32 bit patterns,
// gathered/packed K-major, pads zero-filled.
// ---------------------------------------------------------------------------
__device__ uint32_t g_xtf [(size_t)TOKENS * HIDDEN];   // x, tf32
__device__ uint32_t g_wgtf[(size_t)KPAD   * HIDDEN];   // W_gate[aidx], pad rows = 0
__device__ uint32_t g_wutf[(size_t)KPAD   * HIDDEN];   // W_up[aidx]
__device__ uint32_t g_wdtf[(size_t)HIDDEN * KPAD];     // W_down[:, aidx], pad cols = 0
__device__ uint32_t g_htf [(size_t)TOKENS * KPAD];     // h = silu(g)*u, tf32

__device__ __forceinline__ uint32_t f2tf(float f) {
    uint32_t u; asm("cvt.rna.tf32.f32 %0, %1;" : "=r"(u) : "f"(f)); return u;
}

__device__ __forceinline__ void mma8(float c[4], const uint32_t a[4], const uint32_t b[2]) {
    asm volatile(
        "mma.sync.aligned.m16n8k8.row.col.f32.tf32.tf32.f32 "
        "{%0,%1,%2,%3}, {%4,%5,%6,%7}, {%8,%9}, {%0,%1,%2,%3};\n"
        : "+f"(c[0]), "+f"(c[1]), "+f"(c[2]), "+f"(c[3])
        : "r"(a[0]), "r"(a[1]), "r"(a[2]), "r"(a[3]), "r"(b[0]), "r"(b[1]));
}

__device__ __forceinline__ void cp16(uint32_t s, const void* g) {
    asm volatile("cp.async.cg.shared.global [%0], [%1], 16;\n" :: "r"(s), "l"(g));
}
#define CP_COMMIT() asm volatile("cp.async.commit_group;\n")
#define CP_WAIT1()  asm volatile("cp.async.wait_group 1;\n")

// Per-stage smem (words): gateup (128+64+64)x36, down (128+128)x36 -> both 9216
#define STG_W   9216
#define SMEM_B  (3 * STG_W * 4)     // 110,592 B per CTA; 2 CTAs/SM = 221,184 B

// ---------------------------------------------------------------------------
// Prep kernels: convert + gather + pad once per call (HBM-bound)
// ---------------------------------------------------------------------------
__global__ __launch_bounds__(256) void k_cvt_x(const float* __restrict__ x) {
    size_t i = ((size_t)blockIdx.x * 256 + threadIdx.x) * 4;
    float4 v = *(const float4*)(x + i);
    *(uint4*)(g_xtf + i) = make_uint4(f2tf(v.x), f2tf(v.y), f2tf(v.z), f2tf(v.w));
}
__global__ __launch_bounds__(256) void k_prep_gu(
    const float* __restrict__ Wg, const float* __restrict__ Wu, const int* __restrict__ aidx)
{
    int r = blockIdx.x;
    uint32_t* dg = g_wgtf + (size_t)r * HIDDEN;
    uint32_t* du = g_wutf + (size_t)r * HIDDEN;
    if (r < KACT) {
        int src = __ldg(&aidx[r]);
        const float* sg = Wg + (size_t)src * HIDDEN;
        const float* su = Wu + (size_t)src * HIDDEN;
        for (int c = threadIdx.x * 4; c < HIDDEN; c += 1024) {
            float4 g = *(const float4*)(sg + c);
            float4 u = *(const float4*)(su + c);
            *(uint4*)(dg + c) = make_uint4(f2tf(g.x), f2tf(g.y), f2tf(g.z), f2tf(g.w));
            *(uint4*)(du + c) = make_uint4(f2tf(u.x), f2tf(u.y), f2tf(u.z), f2tf(u.w));
        }
    } else {
        for (int c = threadIdx.x * 4; c < HIDDEN; c += 1024) {
            *(uint4*)(dg + c) = make_uint4(0, 0, 0, 0);
            *(uint4*)(du + c) = make_uint4(0, 0, 0, 0);
        }
    }
}
__global__ __launch_bounds__(256) void k_prep_wd(
    const float* __restrict__ Wd, const int* __restrict__ aidx)
{
    int n = blockIdx.x;
    uint32_t* dst = g_wdtf + (size_t)n * KPAD;
    const float* src = Wd + (size_t)n * INTER;
    for (int k = threadIdx.x; k < KPAD; k += 256)
        dst[k] = (k < KACT) ? f2tf(__ldg(&src[__ldg(&aidx[k])])) : 0u;
}

// ---------------------------------------------------------------------------
// Kernel 1: fused gate+up GEMM + silu epilogue.
// CTA 128(M) x 64(N) DUAL, K step 32. 128 threads, 4 warps (2x2),
// warp tile 64x32 dual. 3-stage cp.async. 2 CTAs/SM (independent barriers).
// Stage layout (words): A@0 (128x36), Bg@4608 (64x36), Bu@6912 (64x36).
// ---------------------------------------------------------------------------
__global__ __launch_bounds__(128, 2) void k_gateup() {
    extern __shared__ uint32_t sm[];
    const int tid = threadIdx.x;
    const uint32_t sbase = (uint32_t)__cvta_generic_to_shared(sm);

    int bid   = blockIdx.x;                     // 64 m-tiles x 52 n-tiles, GRP 8
    int group = bid / (8 * 52);
    int rem   = bid - group * (8 * 52);
    const int bm = (group * 8 + (rem & 7)) * 128;
    const int bn = (rem >> 3) * 64;

    auto load_stage = [&](int s, int kt) {
        const uint32_t base = sbase + (uint32_t)(s * STG_W) * 4;
        const int gk = kt * 32;
#pragma unroll
        for (int i = 0; i < 8; ++i) {           // A: 128 rows = 1024 chunks
            int ch  = tid + 128 * i;
            int row = ch >> 3, c = (ch & 7) * 4;
            cp16(base + (uint32_t)(row * 36 + c) * 4,
                 g_xtf + (size_t)(bm + row) * HIDDEN + gk + c);
        }
#pragma unroll
        for (int i = 0; i < 4; ++i) {           // Bg, Bu: 64 rows = 512 chunks each
            int ch  = tid + 128 * i;
            int row = ch >> 3, c = (ch & 7) * 4;
            uint32_t so = (uint32_t)(row * 36 + c) * 4;
            cp16(base + 4608 * 4 + so, g_wgtf + (size_t)(bn + row) * HIDDEN + gk + c);
            cp16(base + 6912 * 4 + so, g_wutf + (size_t)(bn + row) * HIDDEN + gk + c);
        }
    };

    const int warp = tid >> 5, lane = tid & 31;
    const int wm = (warp & 1) * 64;
    const int wn = (warp >> 1) * 32;
    const int lr4 = lane >> 2, lc4 = lane & 3;

    float accg[4][4][4] = {};
    float accu[4][4][4] = {};

    const int KT = HIDDEN / 32;                 // 128
    load_stage(0, 0); CP_COMMIT();
    load_stage(1, 1); CP_COMMIT();

    int cur = 0;
    for (int kt = 0; kt < KT; ++kt) {
        CP_WAIT1();
        __syncthreads();

        if (kt + 2 < KT) {
            int nxt = cur + 2; if (nxt >= 3) nxt -= 3;
            load_stage(nxt, kt + 2);
        }
        CP_COMMIT();

        const uint32_t* As = sm + cur * STG_W;
        const uint32_t* Bg = As + 4608;
        const uint32_t* Bu = As + 6912;

#pragma unroll
        for (int kk = 0; kk < 4; ++kk) {
            const int kb = kk * 8;
            uint32_t af[4][4];
#pragma unroll
            for (int i = 0; i < 4; ++i) {
                int r = wm + i * 16 + lr4;
                af[i][0] = As[r * 36 + kb + lc4];
                af[i][1] = As[(r + 8) * 36 + kb + lc4];
                af[i][2] = As[r * 36 + kb + lc4 + 4];
                af[i][3] = As[(r + 8) * 36 + kb + lc4 + 4];
            }
            uint32_t bg[4][2], bu[4][2];
#pragma unroll
            for (int j = 0; j < 4; ++j) {
                int n = wn + j * 8 + lr4;
                bg[j][0] = Bg[n * 36 + kb + lc4];
                bg[j][1] = Bg[n * 36 + kb + lc4 + 4];
                bu[j][0] = Bu[n * 36 + kb + lc4];
                bu[j][1] = Bu[n * 36 + kb + lc4 + 4];
            }
#pragma unroll
            for (int i = 0; i < 4; ++i)
#pragma unroll
                for (int j = 0; j < 4; ++j) {
                    mma8(accg[i][j], af[i], bg[j]);
                    mma8(accu[i][j], af[i], bu[j]);
                }
        }
        if (++cur == 3) cur = 0;
    }

    // Epilogue: h = silu(g)*u stored as tf32 bits (pad cols exactly 0)
#pragma unroll
    for (int i = 0; i < 4; ++i)
#pragma unroll
        for (int j = 0; j < 4; ++j) {
            int c0 = bn + wn + j * 8 + 2 * lc4;
#pragma unroll
            for (int half = 0; half < 2; ++half) {
                int r = bm + wm + i * 16 + lr4 + half * 8;
                float g0 = accg[i][j][half * 2], g1 = accg[i][j][half * 2 + 1];
                float u0 = accu[i][j][half * 2], u1 = accu[i][j][half * 2 + 1];
                float h0 = g0 * u0 / (1.0f + __expf(-g0));
                float h1 = g1 * u1 / (1.0f + __expf(-g1));
                *(uint2*)(g_htf + (size_t)r * KPAD + c0) = make_uint2(f2tf(h0), f2tf(h1));
            }
        }
}

// ---------------------------------------------------------------------------
// Kernel 2: out = h @ Wd_packed^T.
// CTA 128(M) x 128(N), K step 32 over KPAD. 128 threads, 4 warps (2x2),
// warp tile 64x64. 3-stage cp.async. 2 CTAs/SM.
// Stage layout (words): A@0 (128x36), B@4608 (128x36).
// ---------------------------------------------------------------------------
__global__ __launch_bounds__(128, 2) void k_down(float* __restrict__ out) {
    extern __shared__ uint32_t sm[];
    const int tid = threadIdx.x;
    const uint32_t sbase = (uint32_t)__cvta_generic_to_shared(sm);

    int bid   = blockIdx.x;                     // 64 m-tiles x 32 n-tiles, GRP 8
    int group = bid / (8 * 32);
    int rem   = bid - group * (8 * 32);
    const int bm = (group * 8 + (rem & 7)) * 128;
    const int bn = (rem >> 3) * 128;

    auto load_stage = [&](int s, int kt) {
        const uint32_t base = sbase + (uint32_t)(s * STG_W) * 4;
        const int gk = kt * 32;
#pragma unroll
        for (int i = 0; i < 8; ++i) {           // A: 128 rows
            int ch  = tid + 128 * i;
            int row = ch >> 3, c = (ch & 7) * 4;
            cp16(base + (uint32_t)(row * 36 + c) * 4,
                 g_htf + (size_t)(bm + row) * KPAD + gk + c);
        }
#pragma unroll
        for (int i = 0; i < 8; ++i) {           // B: 128 rows
            int ch  = tid + 128 * i;
            int row = ch >> 3, c = (ch & 7) * 4;
            cp16(base + 4608 * 4 + (uint32_t)(row * 36 + c) * 4,
                 g_wdtf + (size_t)(bn + row) * KPAD + gk + c);
        }
    };

    const int warp = tid >> 5, lane = tid & 31;
    const int wm = (warp & 1) * 64;
    const int wn = (warp >> 1) * 64;
    const int lr4 = lane >> 2, lc4 = lane & 3;

    float acc[4][8][4] = {};

    const int KT = KPAD / 32;                   // 104
    load_stage(0, 0); CP_COMMIT();
    load_stage(1, 1); CP_COMMIT();

    int cur = 0;
    for (int kt = 0; kt < KT; ++kt) {
        CP_WAIT1();
        __syncthreads();

        if (kt + 2 < KT) {
            int nxt = cur + 2; if (nxt >= 3) nxt -= 3;
            load_stage(nxt, kt + 2);
        }
        CP_COMMIT();

        const uint32_t* As = sm + cur * STG_W;
        const uint32_t* Bs = As + 4608;

#pragma unroll
        for (int kk = 0; kk < 4; ++kk) {
            const int kb = kk * 8;
            uint32_t af[4][4];
#pragma unroll
            for (int i = 0; i < 4; ++i) {
                int r = wm + i * 16 + lr4;
                af[i][0] = As[r * 36 + kb + lc4];
                af[i][1] = As[(r + 8) * 36 + kb + lc4];
                af[i][2] = As[r * 36 + kb + lc4 + 4];
                af[i][3] = As[(r + 8) * 36 + kb + lc4 + 4];
            }
            uint32_t bf[8][2];
#pragma unroll
            for (int j = 0; j < 8; ++j) {
                int n = wn + j * 8 + lr4;
                bf[j][0] = Bs[n * 36 + kb + lc4];
                bf[j][1] = Bs[n * 36 + kb + lc4 + 4];
            }
#pragma unroll
            for (int i = 0; i < 4; ++i)
#pragma unroll
                for (int j = 0; j < 8; ++j)
                    mma8(acc[i][j], af[i], bf[j]);
        }
        if (++cur == 3) cur = 0;
    }

#pragma unroll
    for (int i = 0; i < 4; ++i)
#pragma unroll
        for (int j = 0; j < 8; ++j) {
            int c0 = bn + wn + j * 8 + 2 * lc4;
#pragma unroll
            for (int half = 0; half < 2; ++half) {
                int r = bm + wm + i * 16 + lr4 + half * 8;
                *(float2*)(out + (size_t)r * HIDDEN + c0) =
                    make_float2(acc[i][j][half * 2], acc[i][j][half * 2 + 1]);
            }
        }
}

// ---------------------------------------------------------------------------
// Inputs: x[f32 8192x4096], W_gate[f32 11008x4096], W_up[f32 11008x4096],
// W_down[f32 4096x11008], active_idx[i32 3302]. Output f32 8192x4096.
// ---------------------------------------------------------------------------
extern "C" void kernel_launch(void* const* d_in, const int* in_sizes, int n_in,
                              void* d_out, int out_size)
{
    const float* x    = (const float*)d_in[0];
    const float* Wg   = (const float*)d_in[1];
    const float* Wu   = (const float*)d_in[2];
    const float* Wd   = (const float*)d_in[3];
    const int*   aidx = (const int*)  d_in[4];
    float*       out  = (float*)d_out;

    cudaFuncSetAttribute(k_gateup, cudaFuncAttributeMaxDynamicSharedMemorySize, SMEM_B);
    cudaFuncSetAttribute(k_down,   cudaFuncAttributeMaxDynamicSharedMemorySize, SMEM_B);

    k_cvt_x  <<<(TOKENS * HIDDEN) / 1024, 256>>>(x);
    k_prep_gu<<<KPAD,   256>>>(Wg, Wu, aidx);
    k_prep_wd<<<HIDDEN, 256>>>(Wd, aidx);

    k_gateup<<<(TOKENS / 128) * (KPAD / 64),   128, SMEM_B>>>();      // 64*52 = 3328
    k_down  <<<(TOKENS / 128) * (HIDDEN / 128), 128, SMEM_B>>>(out);  // 64*32 = 2048
}

// round 15
// speedup vs baseline: 1.0787x; 1.0296x over previous
#include <cuda_runtime.h>
#include <cstdint>

#define TOKENS 8192
#define HIDDEN 4096
#define INTER  11008
#define KACT   3302
#define KPAD   3328   // 26 * 128

// ---------------------------------------------------------------------------
// Static device scratch. All operands pre-converted to tf32 bit patterns,
// gathered/packed K-major, pads zero-filled.
// ---------------------------------------------------------------------------
__device__ uint32_t g_xtf [(size_t)TOKENS * HIDDEN];   // x, tf32
__device__ uint32_t g_wgtf[(size_t)KPAD   * HIDDEN];   // W_gate[aidx], pad rows = 0
__device__ uint32_t g_wutf[(size_t)KPAD   * HIDDEN];   // W_up[aidx]
__device__ uint32_t g_wdtf[(size_t)HIDDEN * KPAD];     // W_down[:, aidx], pad cols = 0
__device__ uint32_t g_htf [(size_t)TOKENS * KPAD];     // h = silu(g)*u, tf32

__device__ __forceinline__ uint32_t f2tf(float f) {
    uint32_t u; asm("cvt.rna.tf32.f32 %0, %1;" : "=r"(u) : "f"(f)); return u;
}

__device__ __forceinline__ void mma8(float c[4], const uint32_t a[4], const uint32_t b[2]) {
    asm volatile(
        "mma.sync.aligned.m16n8k8.row.col.f32.tf32.tf32.f32 "
        "{%0,%1,%2,%3}, {%4,%5,%6,%7}, {%8,%9}, {%0,%1,%2,%3};\n"
        : "+f"(c[0]), "+f"(c[1]), "+f"(c[2]), "+f"(c[3])
        : "r"(a[0]), "r"(a[1]), "r"(a[2]), "r"(a[3]), "r"(b[0]), "r"(b[1]));
}

__device__ __forceinline__ void cp16(uint32_t s, const void* g) {
    asm volatile("cp.async.cg.shared.global [%0], [%1], 16;\n" :: "r"(s), "l"(g));
}
#define CP_COMMIT() asm volatile("cp.async.commit_group;\n")
#define CP_WAIT1()  asm volatile("cp.async.wait_group 1;\n")

// K-step 64: rows are 64 data words + 4 pad = 68 words.
// gateup stage: A 256x68 + Bg 64x68 + Bu 64x68 = 26112 words.
// down   stage: A 256x68 + B 128x68           = 26112 words.
#define ROWW   68
#define STG_W  26112
#define SMEM_B (2 * STG_W * 4)      // 208,896 B, 2 stages, 1 CTA/SM

// ---------------------------------------------------------------------------
// Prep kernels: convert + gather + pad once per call (HBM-bound, ~130us)
// ---------------------------------------------------------------------------
__global__ __launch_bounds__(256) void k_cvt_x(const float* __restrict__ x) {
    size_t i = ((size_t)blockIdx.x * 256 + threadIdx.x) * 4;
    float4 v = *(const float4*)(x + i);
    *(uint4*)(g_xtf + i) = make_uint4(f2tf(v.x), f2tf(v.y), f2tf(v.z), f2tf(v.w));
}
__global__ __launch_bounds__(256) void k_prep_gu(
    const float* __restrict__ Wg, const float* __restrict__ Wu, const int* __restrict__ aidx)
{
    int r = blockIdx.x;
    uint32_t* dg = g_wgtf + (size_t)r * HIDDEN;
    uint32_t* du = g_wutf + (size_t)r * HIDDEN;
    if (r < KACT) {
        int src = __ldg(&aidx[r]);
        const float* sg = Wg + (size_t)src * HIDDEN;
        const float* su = Wu + (size_t)src * HIDDEN;
        for (int c = threadIdx.x * 4; c < HIDDEN; c += 1024) {
            float4 g = *(const float4*)(sg + c);
            float4 u = *(const float4*)(su + c);
            *(uint4*)(dg + c) = make_uint4(f2tf(g.x), f2tf(g.y), f2tf(g.z), f2tf(g.w));
            *(uint4*)(du + c) = make_uint4(f2tf(u.x), f2tf(u.y), f2tf(u.z), f2tf(u.w));
        }
    } else {
        for (int c = threadIdx.x * 4; c < HIDDEN; c += 1024) {
            *(uint4*)(dg + c) = make_uint4(0, 0, 0, 0);
            *(uint4*)(du + c) = make_uint4(0, 0, 0, 0);
        }
    }
}
__global__ __launch_bounds__(256) void k_prep_wd(
    const float* __restrict__ Wd, const int* __restrict__ aidx)
{
    int n = blockIdx.x;
    uint32_t* dst = g_wdtf + (size_t)n * KPAD;
    const float* src = Wd + (size_t)n * INTER;
    for (int k = threadIdx.x; k < KPAD; k += 256)
        dst[k] = (k < KACT) ? f2tf(__ldg(&src[__ldg(&aidx[k])])) : 0u;
}

// ---------------------------------------------------------------------------
// Kernel 1: fused gate+up GEMM + silu epilogue.
// CTA 256(M) x 64(N) DUAL, K step 64 over HIDDEN. 256 threads, 8 warps (4x2),
// warp tile 64x32 dual. 2-stage cp.async double buffer.
// Stage layout (words): A@0 (256x68), Bg@17408 (64x68), Bu@21760 (64x68).
// ---------------------------------------------------------------------------
__global__ __launch_bounds__(256, 1) void k_gateup() {
    extern __shared__ uint32_t sm[];
    const int tid = threadIdx.x;
    const uint32_t sbase = (uint32_t)__cvta_generic_to_shared(sm);

    int bid   = blockIdx.x;                     // 32 m-tiles x 52 n-tiles, GRP 8
    int group = bid / (8 * 52);
    int rem   = bid - group * (8 * 52);
    const int bm = (group * 8 + (rem & 7)) * 256;
    const int bn = (rem >> 3) * 64;

    auto load_stage = [&](int s, int kt) {
        const uint32_t base = sbase + (uint32_t)(s * STG_W) * 4;
        const int gk = kt * 64;
#pragma unroll
        for (int i = 0; i < 16; ++i) {          // A: 256 rows x 16 chunks = 4096
            int ch  = tid + 256 * i;
            int row = ch >> 4, c = (ch & 15) * 4;
            cp16(base + (uint32_t)(row * ROWW + c) * 4,
                 g_xtf + (size_t)(bm + row) * HIDDEN + gk + c);
        }
#pragma unroll
        for (int i = 0; i < 4; ++i) {           // Bg, Bu: 64 rows x 16 chunks = 1024 each
            int ch  = tid + 256 * i;
            int row = ch >> 4, c = (ch & 15) * 4;
            uint32_t so = (uint32_t)(row * ROWW + c) * 4;
            cp16(base + 17408 * 4 + so, g_wgtf + (size_t)(bn + row) * HIDDEN + gk + c);
            cp16(base + 21760 * 4 + so, g_wutf + (size_t)(bn + row) * HIDDEN + gk + c);
        }
    };

    const int warp = tid >> 5, lane = tid & 31;
    const int wm = (warp & 3) * 64;
    const int wn = (warp >> 2) * 32;
    const int lr4 = lane >> 2, lc4 = lane & 3;

    float accg[4][4][4] = {};
    float accu[4][4][4] = {};

    const int KT = HIDDEN / 64;                 // 64
    load_stage(0, 0); CP_COMMIT();
    load_stage(1, 1); CP_COMMIT();

    for (int kt = 0; kt < KT; ++kt) {
        const int cur = kt & 1;
        CP_WAIT1();
        __syncthreads();

        const uint32_t* As = sm + cur * STG_W;
        const uint32_t* Bg = As + 17408;
        const uint32_t* Bu = As + 21760;
#pragma unroll
        for (int kk = 0; kk < 8; ++kk) {
            const int kb = kk * 8;
            uint32_t af[4][4];
#pragma unroll
            for (int i = 0; i < 4; ++i) {
                int r = wm + i * 16 + lr4;
                af[i][0] = As[r * ROWW + kb + lc4];
                af[i][1] = As[(r + 8) * ROWW + kb + lc4];
                af[i][2] = As[r * ROWW + kb + lc4 + 4];
                af[i][3] = As[(r + 8) * ROWW + kb + lc4 + 4];
            }
            uint32_t bg[4][2], bu[4][2];
#pragma unroll
            for (int j = 0; j < 4; ++j) {
                int n = wn + j * 8 + lr4;
                bg[j][0] = Bg[n * ROWW + kb + lc4];
                bg[j][1] = Bg[n * ROWW + kb + lc4 + 4];
                bu[j][0] = Bu[n * ROWW + kb + lc4];
                bu[j][1] = Bu[n * ROWW + kb + lc4 + 4];
            }
#pragma unroll
            for (int i = 0; i < 4; ++i)
#pragma unroll
                for (int j = 0; j < 4; ++j) {
                    mma8(accg[i][j], af[i], bg[j]);
                    mma8(accu[i][j], af[i], bu[j]);
                }
        }

        __syncthreads();                        // all warps done reading stage cur
        if (kt + 2 < KT) load_stage(cur, kt + 2);
        CP_COMMIT();
    }

    // Epilogue: h = silu(g)*u stored as tf32 bits (pad cols exactly 0)
#pragma unroll
    for (int i = 0; i < 4; ++i)
#pragma unroll
        for (int j = 0; j < 4; ++j) {
            int c0 = bn + wn + j * 8 + 2 * lc4;
#pragma unroll
            for (int half = 0; half < 2; ++half) {
                int r = bm + wm + i * 16 + lr4 + half * 8;
                float g0 = accg[i][j][half * 2], g1 = accg[i][j][half * 2 + 1];
                float u0 = accu[i][j][half * 2], u1 = accu[i][j][half * 2 + 1];
                float h0 = g0 * u0 / (1.0f + __expf(-g0));
                float h1 = g1 * u1 / (1.0f + __expf(-g1));
                *(uint2*)(g_htf + (size_t)r * KPAD + c0) = make_uint2(f2tf(h0), f2tf(h1));
            }
        }
}

// ---------------------------------------------------------------------------
// Kernel 2: out = h @ Wd_packed^T.
// CTA 256(M) x 128(N), K step 64 over KPAD. 256 threads, 8 warps (4x2),
// warp tile 64x64. 2-stage cp.async.
// Stage layout (words): A@0 (256x68), B@17408 (128x68).
// ---------------------------------------------------------------------------
__global__ __launch_bounds__(256, 1) void k_down(float* __restrict__ out) {
    extern __shared__ uint32_t sm[];
    const int tid = threadIdx.x;
    const uint32_t sbase = (uint32_t)__cvta_generic_to_shared(sm);

    int bid   = blockIdx.x;                     // 32 m-tiles x 32 n-tiles, GRP 8
    int group = bid / (8 * 32);
    int rem   = bid - group * (8 * 32);
    const int bm = (group * 8 + (rem & 7)) * 256;
    const int bn = (rem >> 3) * 128;

    auto load_stage = [&](int s, int kt) {
        const uint32_t base = sbase + (uint32_t)(s * STG_W) * 4;
        const int gk = kt * 64;
#pragma unroll
        for (int i = 0; i < 16; ++i) {          // A: 256 rows
            int ch  = tid + 256 * i;
            int row = ch >> 4, c = (ch & 15) * 4;
            cp16(base + (uint32_t)(row * ROWW + c) * 4,
                 g_htf + (size_t)(bm + row) * KPAD + gk + c);
        }
#pragma unroll
        for (int i = 0; i < 8; ++i) {           // B: 128 rows
            int ch  = tid + 256 * i;
            int row = ch >> 4, c = (ch & 15) * 4;
            cp16(base + 17408 * 4 + (uint32_t)(row * ROWW + c) * 4,
                 g_wdtf + (size_t)(bn + row) * KPAD + gk + c);
        }
    };

    const int warp = tid >> 5, lane = tid & 31;
    const int wm = (warp & 3) * 64;
    const int wn = (warp >> 2) * 64;
    const int lr4 = lane >> 2, lc4 = lane & 3;

    float acc[4][8][4] = {};

    const int KT = KPAD / 64;                   // 52
    load_stage(0, 0); CP_COMMIT();
    load_stage(1, 1); CP_COMMIT();

    for (int kt = 0; kt < KT; ++kt) {
        const int cur = kt & 1;
        CP_WAIT1();
        __syncthreads();

        const uint32_t* As = sm + cur * STG_W;
        const uint32_t* Bs = As + 17408;
#pragma unroll
        for (int kk = 0; kk < 8; ++kk) {
            const int kb = kk * 8;
            uint32_t af[4][4];
#pragma unroll
            for (int i = 0; i < 4; ++i) {
                int r = wm + i * 16 + lr4;
                af[i][0] = As[r * ROWW + kb + lc4];
                af[i][1] = As[(r + 8) * ROWW + kb + lc4];
                af[i][2] = As[r * ROWW + kb + lc4 + 4];
                af[i][3] = As[(r + 8) * ROWW + kb + lc4 + 4];
            }
            uint32_t bf[8][2];
#pragma unroll
            for (int j = 0; j < 8; ++j) {
                int n = wn + j * 8 + lr4;
                bf[j][0] = Bs[n * ROWW + kb + lc4];
                bf[j][1] = Bs[n * ROWW + kb + lc4 + 4];
            }
#pragma unroll
            for (int i = 0; i < 4; ++i)
#pragma unroll
                for (int j = 0; j < 8; ++j)
                    mma8(acc[i][j], af[i], bf[j]);
        }

        __syncthreads();
        if (kt + 2 < KT) load_stage(cur, kt + 2);
        CP_COMMIT();
    }

#pragma unroll
    for (int i = 0; i < 4; ++i)
#pragma unroll
        for (int j = 0; j < 8; ++j) {
            int c0 = bn + wn + j * 8 + 2 * lc4;
#pragma unroll
            for (int half = 0; half < 2; ++half) {
                int r = bm + wm + i * 16 + lr4 + half * 8;
                *(float2*)(out + (size_t)r * HIDDEN + c0) =
                    make_float2(acc[i][j][half * 2], acc[i][j][half * 2 + 1]);
            }
        }
}

// ---------------------------------------------------------------------------
// Inputs: x[f32 8192x4096], W_gate[f32 11008x4096], W_up[f32 11008x4096],
// W_down[f32 4096x11008], active_idx[i32 3302]. Output f32 8192x4096.
// ---------------------------------------------------------------------------
extern "C" void kernel_launch(void* const* d_in, const int* in_sizes, int n_in,
                              void* d_out, int out_size)
{
    const float* x    = (const float*)d_in[0];
    const float* Wg   = (const float*)d_in[1];
    const float* Wu   = (const float*)d_in[2];
    const float* Wd   = (const float*)d_in[3];
    const int*   aidx = (const int*)  d_in[4];
    float*       out  = (float*)d_out;

    cudaFuncSetAttribute(k_gateup, cudaFuncAttributeMaxDynamicSharedMemorySize, SMEM_B);
    cudaFuncSetAttribute(k_down,   cudaFuncAttributeMaxDynamicSharedMemorySize, SMEM_B);

    k_cvt_x  <<<(TOKENS * HIDDEN) / 1024, 256>>>(x);
    k_prep_gu<<<KPAD,   256>>>(Wg, Wu, aidx);
    k_prep_wd<<<HIDDEN, 256>>>(Wd, aidx);

    k_gateup<<<(TOKENS / 256) * (KPAD / 64),    256, SMEM_B>>>();     // 32*52 = 1664
    k_down  <<<(TOKENS / 256) * (HIDDEN / 128), 256, SMEM_B>>>(out);  // 32*32 = 1024
}

// round 16
// speedup vs baseline: 2.0764x; 1.9248x over previous
#include <cuda_runtime.h>
#include <cuda_fp16.h>
#include <cstdint>

#define TOKENS 8192
#define HIDDEN 4096
#define INTER  11008
#define KACT   3302
#define KPAD   3328   // 26 * 128

#define HW_X (HIDDEN / 2)   // 2048 words per row (x, wg, wu)
#define HW_K (KPAD / 2)     // 1664 words per row (wd, h)

// ---------------------------------------------------------------------------
// Static device scratch: fp16 pairs packed in u32 (2 halves along K per word).
// Gathered/packed, pads zero-filled.
// ---------------------------------------------------------------------------
__device__ uint32_t g_xh [(size_t)TOKENS * HW_X];
__device__ uint32_t g_wgh[(size_t)KPAD   * HW_X];
__device__ uint32_t g_wuh[(size_t)KPAD   * HW_X];
__device__ uint32_t g_wdh[(size_t)HIDDEN * HW_K];
__device__ uint32_t g_hh [(size_t)TOKENS * HW_K];

__device__ __forceinline__ uint32_t pack2(float a, float b) {
    __half2 h = __floats2half2_rn(a, b);
    return *(uint32_t*)&h;
}

// fp16 m16n8k16: same fragment shape as tf32 m16n8k8, 2x MACs per instruction.
__device__ __forceinline__ void mma16(float c[4], const uint32_t a[4], const uint32_t b[2]) {
    asm volatile(
        "mma.sync.aligned.m16n8k16.row.col.f32.f16.f16.f32 "
        "{%0,%1,%2,%3}, {%4,%5,%6,%7}, {%8,%9}, {%0,%1,%2,%3};\n"
        : "+f"(c[0]), "+f"(c[1]), "+f"(c[2]), "+f"(c[3])
        : "r"(a[0]), "r"(a[1]), "r"(a[2]), "r"(a[3]), "r"(b[0]), "r"(b[1]));
}

__device__ __forceinline__ void cp16(uint32_t s, const void* g) {
    asm volatile("cp.async.cg.shared.global [%0], [%1], 16;\n" :: "r"(s), "l"(g));
}
#define CP_COMMIT() asm volatile("cp.async.commit_group;\n")
#define CP_WAIT1()  asm volatile("cp.async.wait_group 1;\n")

// K-step 128 elements = 64 words; rows 64 data + 4 pad = 68 words.
// gateup stage: A 256x68 + Bg 64x68 + Bu 64x68 = 26112 words.
// down   stage: A 256x68 + B 128x68           = 26112 words.
#define ROWW   68
#define STG_W  26112
#define SMEM_B (2 * STG_W * 4)      // 208,896 B, 2 stages, 1 CTA/SM

// ---------------------------------------------------------------------------
// Prep kernels: convert fp32 -> packed fp16, gather, pad (HBM-bound, ~100us)
// ---------------------------------------------------------------------------
__global__ __launch_bounds__(256) void k_cvt_x(const float* __restrict__ x) {
    size_t i = ((size_t)blockIdx.x * 256 + threadIdx.x) * 4;   // element idx
    float4 v = *(const float4*)(x + i);
    *(uint2*)(g_xh + i / 2) = make_uint2(pack2(v.x, v.y), pack2(v.z, v.w));
}
__global__ __launch_bounds__(256) void k_prep_gu(
    const float* __restrict__ Wg, const float* __restrict__ Wu, const int* __restrict__ aidx)
{
    int r = blockIdx.x;
    uint32_t* dg = g_wgh + (size_t)r * HW_X;
    uint32_t* du = g_wuh + (size_t)r * HW_X;
    if (r < KACT) {
        int src = __ldg(&aidx[r]);
        const float* sg = Wg + (size_t)src * HIDDEN;
        const float* su = Wu + (size_t)src * HIDDEN;
        for (int c = threadIdx.x * 4; c < HIDDEN; c += 1024) {
            float4 g = *(const float4*)(sg + c);
            float4 u = *(const float4*)(su + c);
            *(uint2*)(dg + c / 2) = make_uint2(pack2(g.x, g.y), pack2(g.z, g.w));
            *(uint2*)(du + c / 2) = make_uint2(pack2(u.x, u.y), pack2(u.z, u.w));
        }
    } else {
        for (int c = threadIdx.x * 4; c < HIDDEN; c += 1024) {
            *(uint2*)(dg + c / 2) = make_uint2(0, 0);
            *(uint2*)(du + c / 2) = make_uint2(0, 0);
        }
    }
}
__global__ __launch_bounds__(256) void k_prep_wd(
    const float* __restrict__ Wd, const int* __restrict__ aidx)
{
    int n = blockIdx.x;
    uint32_t* dst = g_wdh + (size_t)n * HW_K;
    const float* src = Wd + (size_t)n * INTER;
    for (int w = threadIdx.x; w < HW_K; w += 256) {
        int k = 2 * w;                          // KACT even -> pair never straddles
        dst[w] = (k < KACT)
            ? pack2(__ldg(&src[__ldg(&aidx[k])]), __ldg(&src[__ldg(&aidx[k + 1])]))
            : 0u;
    }
}

// ---------------------------------------------------------------------------
// Kernel 1: fused gate+up GEMM + silu epilogue.
// CTA 256(M) x 64(N) DUAL, K step 128 elems over HIDDEN. 256 threads, 8 warps
// (4x2), warp tile 64x32 dual, fp16 m16n8k16. 2-stage cp.async double buffer.
// Stage layout (words): A@0 (256x68), Bg@17408 (64x68), Bu@21760 (64x68).
// ---------------------------------------------------------------------------
__global__ __launch_bounds__(256, 1) void k_gateup() {
    extern __shared__ uint32_t sm[];
    const int tid = threadIdx.x;
    const uint32_t sbase = (uint32_t)__cvta_generic_to_shared(sm);

    int bid   = blockIdx.x;                     // 32 m-tiles x 52 n-tiles, GRP 8
    int group = bid / (8 * 52);
    int rem   = bid - group * (8 * 52);
    const int bm = (group * 8 + (rem & 7)) * 256;
    const int bn = (rem >> 3) * 64;

    auto load_stage = [&](int s, int kt) {
        const uint32_t base = sbase + (uint32_t)(s * STG_W) * 4;
        const int gk = kt * 64;                 // word offset along K
#pragma unroll
        for (int i = 0; i < 16; ++i) {          // A: 256 rows x 16 chunks
            int ch  = tid + 256 * i;
            int row = ch >> 4, c = (ch & 15) * 4;
            cp16(base + (uint32_t)(row * ROWW + c) * 4,
                 g_xh + (size_t)(bm + row) * HW_X + gk + c);
        }
#pragma unroll
        for (int i = 0; i < 4; ++i) {           // Bg, Bu: 64 rows x 16 chunks
            int ch  = tid + 256 * i;
            int row = ch >> 4, c = (ch & 15) * 4;
            uint32_t so = (uint32_t)(row * ROWW + c) * 4;
            cp16(base + 17408 * 4 + so, g_wgh + (size_t)(bn + row) * HW_X + gk + c);
            cp16(base + 21760 * 4 + so, g_wuh + (size_t)(bn + row) * HW_X + gk + c);
        }
    };

    const int warp = tid >> 5, lane = tid & 31;
    const int wm = (warp & 3) * 64;
    const int wn = (warp >> 2) * 32;
    const int lr4 = lane >> 2, lc4 = lane & 3;

    float accg[4][4][4] = {};
    float accu[4][4][4] = {};

    const int KT = HIDDEN / 128;                // 32
    load_stage(0, 0); CP_COMMIT();
    load_stage(1, 1); CP_COMMIT();

    for (int kt = 0; kt < KT; ++kt) {
        const int cur = kt & 1;
        CP_WAIT1();
        __syncthreads();

        const uint32_t* As = sm + cur * STG_W;
        const uint32_t* Bg = As + 17408;
        const uint32_t* Bu = As + 21760;
#pragma unroll
        for (int kk = 0; kk < 8; ++kk) {        // 8 x K16 = 128 elements
            const int kb = kk * 8;
            uint32_t af[4][4];
#pragma unroll
            for (int i = 0; i < 4; ++i) {
                int r = wm + i * 16 + lr4;
                af[i][0] = As[r * ROWW + kb + lc4];
                af[i][1] = As[(r + 8) * ROWW + kb + lc4];
                af[i][2] = As[r * ROWW + kb + lc4 + 4];
                af[i][3] = As[(r + 8) * ROWW + kb + lc4 + 4];
            }
            uint32_t bg[4][2], bu[4][2];
#pragma unroll
            for (int j = 0; j < 4; ++j) {
                int n = wn + j * 8 + lr4;
                bg[j][0] = Bg[n * ROWW + kb + lc4];
                bg[j][1] = Bg[n * ROWW + kb + lc4 + 4];
                bu[j][0] = Bu[n * ROWW + kb + lc4];
                bu[j][1] = Bu[n * ROWW + kb + lc4 + 4];
            }
#pragma unroll
            for (int i = 0; i < 4; ++i)
#pragma unroll
                for (int j = 0; j < 4; ++j) {
                    mma16(accg[i][j], af[i], bg[j]);
                    mma16(accu[i][j], af[i], bu[j]);
                }
        }

        __syncthreads();
        if (kt + 2 < KT) load_stage(cur, kt + 2);
        CP_COMMIT();
    }

    // Epilogue: h = silu(g)*u stored as fp16 pairs (pad cols exactly 0).
    // c0 even -> word index (bn+wn+j*8)/2 + lc4.
#pragma unroll
    for (int i = 0; i < 4; ++i)
#pragma unroll
        for (int j = 0; j < 4; ++j) {
            int c0 = bn + wn + j * 8 + 2 * lc4;
#pragma unroll
            for (int half = 0; half < 2; ++half) {
                int r = bm + wm + i * 16 + lr4 + half * 8;
                float g0 = accg[i][j][half * 2], g1 = accg[i][j][half * 2 + 1];
                float u0 = accu[i][j][half * 2], u1 = accu[i][j][half * 2 + 1];
                float h0 = g0 * u0 / (1.0f + __expf(-g0));
                float h1 = g1 * u1 / (1.0f + __expf(-g1));
                g_hh[(size_t)r * HW_K + c0 / 2] = pack2(h0, h1);
            }
        }
}

// ---------------------------------------------------------------------------
// Kernel 2: out = h @ Wd_packed^T.
// CTA 256(M) x 128(N), K step 128 elems over KPAD. 256 threads, 8 warps (4x2),
// warp tile 64x64, fp16 m16n8k16. 2-stage cp.async.
// Stage layout (words): A@0 (256x68), B@17408 (128x68).
// ---------------------------------------------------------------------------
__global__ __launch_bounds__(256, 1) void k_down(float* __restrict__ out) {
    extern __shared__ uint32_t sm[];
    const int tid = threadIdx.x;
    const uint32_t sbase = (uint32_t)__cvta_generic_to_shared(sm);

    int bid   = blockIdx.x;                     // 32 m-tiles x 32 n-tiles, GRP 8
    int group = bid / (8 * 32);
    int rem   = bid - group * (8 * 32);
    const int bm = (group * 8 + (rem & 7)) * 256;
    const int bn = (rem >> 3) * 128;

    auto load_stage = [&](int s, int kt) {
        const uint32_t base = sbase + (uint32_t)(s * STG_W) * 4;
        const int gk = kt * 64;
#pragma unroll
        for (int i = 0; i < 16; ++i) {          // A: 256 rows
            int ch  = tid + 256 * i;
            int row = ch >> 4, c = (ch & 15) * 4;
            cp16(base + (uint32_t)(row * ROWW + c) * 4,
                 g_hh + (size_t)(bm + row) * HW_K + gk + c);
        }
#pragma unroll
        for (int i = 0; i < 8; ++i) {           // B: 128 rows
            int ch  = tid + 256 * i;
            int row = ch >> 4, c = (ch & 15) * 4;
            cp16(base + 17408 * 4 + (uint32_t)(row * ROWW + c) * 4,
                 g_wdh + (size_t)(bn + row) * HW_K + gk + c);
        }
    };

    const int warp = tid >> 5, lane = tid & 31;
    const int wm = (warp & 3) * 64;
    const int wn = (warp >> 2) * 64;
    const int lr4 = lane >> 2, lc4 = lane & 3;

    float acc[4][8][4] = {};

    const int KT = KPAD / 128;                  // 26
    load_stage(0, 0); CP_COMMIT();
    load_stage(1, 1); CP_COMMIT();

    for (int kt = 0; kt < KT; ++kt) {
        const int cur = kt & 1;
        CP_WAIT1();
        __syncthreads();

        const uint32_t* As = sm + cur * STG_W;
        const uint32_t* Bs = As + 17408;
#pragma unroll
        for (int kk = 0; kk < 8; ++kk) {
            const int kb = kk * 8;
            uint32_t af[4][4];
#pragma unroll
            for (int i = 0; i < 4; ++i) {
                int r = wm + i * 16 + lr4;
                af[i][0] = As[r * ROWW + kb + lc4];
                af[i][1] = As[(r + 8) * ROWW + kb + lc4];
                af[i][2] = As[r * ROWW + kb + lc4 + 4];
                af[i][3] = As[(r + 8) * ROWW + kb + lc4 + 4];
            }
            uint32_t bf[8][2];
#pragma unroll
            for (int j = 0; j < 8; ++j) {
                int n = wn + j * 8 + lr4;
                bf[j][0] = Bs[n * ROWW + kb + lc4];
                bf[j][1] = Bs[n * ROWW + kb + lc4 + 4];
            }
#pragma unroll
            for (int i = 0; i < 4; ++i)
#pragma unroll
                for (int j = 0; j < 8; ++j)
                    mma16(acc[i][j], af[i], bf[j]);
        }

        __syncthreads();
        if (kt + 2 < KT) load_stage(cur, kt + 2);
        CP_COMMIT();
    }

#pragma unroll
    for (int i = 0; i < 4; ++i)
#pragma unroll
        for (int j = 0; j < 8; ++j) {
            int c0 = bn + wn + j * 8 + 2 * lc4;
#pragma unroll
            for (int half = 0; half < 2; ++half) {
                int r = bm + wm + i * 16 + lr4 + half * 8;
                *(float2*)(out + (size_t)r * HIDDEN + c0) =
                    make_float2(acc[i][j][half * 2], acc[i][j][half * 2 + 1]);
            }
        }
}

// ---------------------------------------------------------------------------
// Inputs: x[f32 8192x4096], W_gate[f32 11008x4096], W_up[f32 11008x4096],
// W_down[f32 4096x11008], active_idx[i32 3302]. Output f32 8192x4096.
// ---------------------------------------------------------------------------
extern "C" void kernel_launch(void* const* d_in, const int* in_sizes, int n_in,
                              void* d_out, int out_size)
{
    const float* x    = (const float*)d_in[0];
    const float* Wg   = (const float*)d_in[1];
    const float* Wu   = (const float*)d_in[2];
    const float* Wd   = (const float*)d_in[3];
    const int*   aidx = (const int*)  d_in[4];
    float*       out  = (float*)d_out;

    cudaFuncSetAttribute(k_gateup, cudaFuncAttributeMaxDynamicSharedMemorySize, SMEM_B);
    cudaFuncSetAttribute(k_down,   cudaFuncAttributeMaxDynamicSharedMemorySize, SMEM_B);

    k_cvt_x  <<<(TOKENS * HIDDEN) / 1024, 256>>>(x);
    k_prep_gu<<<KPAD,   256>>>(Wg, Wu, aidx);
    k_prep_wd<<<HIDDEN, 256>>>(Wd, aidx);

    k_gateup<<<(TOKENS / 256) * (KPAD / 64),    256, SMEM_B>>>();     // 32*52 = 1664
    k_down  <<<(TOKENS / 256) * (HIDDEN / 128), 256, SMEM_B>>>(out);  // 32*32 = 1024
}

// round 17
// speedup vs baseline: 2.1138x; 1.0180x over previous
#include <cuda_runtime.h>
#include <cuda_fp16.h>
#include <cstdint>

#define TOKENS 8192
#define HIDDEN 4096
#define INTER  11008
#define KACT   3302
#define KPAD   3328   // 26 * 128

#define HW_X (HIDDEN / 2)   // 2048 words per row (x, wg, wu)
#define HW_K (KPAD / 2)     // 1664 words per row (wd, h)

// ---------------------------------------------------------------------------
// Static device scratch: fp16 pairs packed in u32 (2 halves along K per word).
// Gathered/packed, pads zero-filled.
// ---------------------------------------------------------------------------
__device__ uint32_t g_xh [(size_t)TOKENS * HW_X];
__device__ uint32_t g_wgh[(size_t)KPAD   * HW_X];
__device__ uint32_t g_wuh[(size_t)KPAD   * HW_X];
__device__ uint32_t g_wdh[(size_t)HIDDEN * HW_K];
__device__ uint32_t g_hh [(size_t)TOKENS * HW_K];

__device__ __forceinline__ uint32_t pack2(float a, float b) {
    __half2 h = __floats2half2_rn(a, b);
    return *(uint32_t*)&h;
}

__device__ __forceinline__ void mma16(float c[4], const uint32_t a[4], const uint32_t b[2]) {
    asm volatile(
        "mma.sync.aligned.m16n8k16.row.col.f32.f16.f16.f32 "
        "{%0,%1,%2,%3}, {%4,%5,%6,%7}, {%8,%9}, {%0,%1,%2,%3};\n"
        : "+f"(c[0]), "+f"(c[1]), "+f"(c[2]), "+f"(c[3])
        : "r"(a[0]), "r"(a[1]), "r"(a[2]), "r"(a[3]), "r"(b[0]), "r"(b[1]));
}

// ldmatrix x4: one instruction loads four 8x8 b16 tiles (4 fragment regs).
__device__ __forceinline__ void ldsm4(uint32_t* r, uint32_t a) {
    asm volatile("ldmatrix.sync.aligned.m8n8.x4.shared.b16 {%0,%1,%2,%3}, [%4];"
        : "=r"(r[0]), "=r"(r[1]), "=r"(r[2]), "=r"(r[3]) : "r"(a));
}

__device__ __forceinline__ void cp16(uint32_t s, const void* g) {
    asm volatile("cp.async.cg.shared.global [%0], [%1], 16;\n" :: "r"(s), "l"(g));
}
#define CP_COMMIT() asm volatile("cp.async.commit_group;\n")
#define CP_WAIT1()  asm volatile("cp.async.wait_group 1;\n")

// K-step 128 elements = 64 words; rows 64 data + 4 pad = 68 words.
#define ROWW   68
#define STG_W  26112
#define SMEM_B (2 * STG_W * 4)      // 208,896 B, 2 stages, 1 CTA/SM

// ---------------------------------------------------------------------------
// Prep kernels: convert fp32 -> packed fp16, gather, pad (HBM-bound, ~100us)
// ---------------------------------------------------------------------------
__global__ __launch_bounds__(256) void k_cvt_x(const float* __restrict__ x) {
    size_t i = ((size_t)blockIdx.x * 256 + threadIdx.x) * 4;
    float4 v = *(const float4*)(x + i);
    *(uint2*)(g_xh + i / 2) = make_uint2(pack2(v.x, v.y), pack2(v.z, v.w));
}
__global__ __launch_bounds__(256) void k_prep_gu(
    const float* __restrict__ Wg, const float* __restrict__ Wu, const int* __restrict__ aidx)
{
    int r = blockIdx.x;
    uint32_t* dg = g_wgh + (size_t)r * HW_X;
    uint32_t* du = g_wuh + (size_t)r * HW_X;
    if (r < KACT) {
        int src = __ldg(&aidx[r]);
        const float* sg = Wg + (size_t)src * HIDDEN;
        const float* su = Wu + (size_t)src * HIDDEN;
        for (int c = threadIdx.x * 4; c < HIDDEN; c += 1024) {
            float4 g = *(const float4*)(sg + c);
            float4 u = *(const float4*)(su + c);
            *(uint2*)(dg + c / 2) = make_uint2(pack2(g.x, g.y), pack2(g.z, g.w));
            *(uint2*)(du + c / 2) = make_uint2(pack2(u.x, u.y), pack2(u.z, u.w));
        }
    } else {
        for (int c = threadIdx.x * 4; c < HIDDEN; c += 1024) {
            *(uint2*)(dg + c / 2) = make_uint2(0, 0);
            *(uint2*)(du + c / 2) = make_uint2(0, 0);
        }
    }
}
__global__ __launch_bounds__(256) void k_prep_wd(
    const float* __restrict__ Wd, const int* __restrict__ aidx)
{
    int n = blockIdx.x;
    uint32_t* dst = g_wdh + (size_t)n * HW_K;
    const float* src = Wd + (size_t)n * INTER;
    for (int w = threadIdx.x; w < HW_K; w += 256) {
        int k = 2 * w;
        dst[w] = (k < KACT)
            ? pack2(__ldg(&src[__ldg(&aidx[k])]), __ldg(&src[__ldg(&aidx[k + 1])]))
            : 0u;
    }
}

// ---------------------------------------------------------------------------
// Kernel 1: fused gate+up GEMM + silu epilogue.
// CTA 256(M) x 64(N) DUAL, K step 128 elems. 256 threads, 8 warps (4x2),
// warp tile 64x32 dual, fp16 m16n8k16, ldmatrix.x4 fragment loads.
// Stage layout (words): A@0 (256x68), Bg@17408 (64x68), Bu@21760 (64x68).
// ---------------------------------------------------------------------------
__global__ __launch_bounds__(256, 1) void k_gateup() {
    extern __shared__ uint32_t sm[];
    const int tid = threadIdx.x;
    const uint32_t sbase = (uint32_t)__cvta_generic_to_shared(sm);

    int bid   = blockIdx.x;                     // 32 m-tiles x 52 n-tiles, GRP 8
    int group = bid / (8 * 52);
    int rem   = bid - group * (8 * 52);
    const int bm = (group * 8 + (rem & 7)) * 256;
    const int bn = (rem >> 3) * 64;

    auto load_stage = [&](int s, int kt) {
        const uint32_t base = sbase + (uint32_t)(s * STG_W) * 4;
        const int gk = kt * 64;
#pragma unroll
        for (int i = 0; i < 16; ++i) {
            int ch  = tid + 256 * i;
            int row = ch >> 4, c = (ch & 15) * 4;
            cp16(base + (uint32_t)(row * ROWW + c) * 4,
                 g_xh + (size_t)(bm + row) * HW_X + gk + c);
        }
#pragma unroll
        for (int i = 0; i < 4; ++i) {
            int ch  = tid + 256 * i;
            int row = ch >> 4, c = (ch & 15) * 4;
            uint32_t so = (uint32_t)(row * ROWW + c) * 4;
            cp16(base + 17408 * 4 + so, g_wgh + (size_t)(bn + row) * HW_X + gk + c);
            cp16(base + 21760 * 4 + so, g_wuh + (size_t)(bn + row) * HW_X + gk + c);
        }
    };

    const int warp = tid >> 5, lane = tid & 31;
    const int wm = (warp & 3) * 64;
    const int wn = (warp >> 2) * 32;
    const int lr4 = lane >> 2, lc4 = lane & 3;

    // ldmatrix per-lane offsets (bytes, relative to stage base).
    // A x4: q0 m-lo/k-lo, q1 m-hi/k-lo, q2 m-lo/k-hi, q3 m-hi/k-hi.
    uint32_t a_off[4];
#pragma unroll
    for (int i = 0; i < 4; ++i) {
        int row = wm + i * 16 + ((lane >> 3) & 1) * 8 + (lane & 7);
        a_off[i] = (uint32_t)(row * ROWW + ((lane >> 4) & 1) * 4) * 4;
    }
    // B x4 covers j-pair (2p, 2p+1): q0 j/k-lo, q1 j/k-hi, q2 j+1/k-lo, q3 j+1/k-hi.
    uint32_t bg_off[1], bu_off[1];
    {
        int row = wn + ((lane >> 4) & 1) * 8 + (lane & 7);
        uint32_t ro = (uint32_t)(row * ROWW + ((lane >> 3) & 1) * 4) * 4;
        bg_off[0] = 17408u * 4 + ro;
        bu_off[0] = 21760u * 4 + ro;
    }

    float accg[4][4][4] = {};
    float accu[4][4][4] = {};

    const int KT = HIDDEN / 128;                // 32
    load_stage(0, 0); CP_COMMIT();
    load_stage(1, 1); CP_COMMIT();

    for (int kt = 0; kt < KT; ++kt) {
        const int cur = kt & 1;
        CP_WAIT1();
        __syncthreads();

        const uint32_t st = sbase + (uint32_t)(cur * STG_W) * 4;
#pragma unroll
        for (int kk = 0; kk < 8; ++kk) {
            const uint32_t kbb = kk * 32;       // 8 words = 32 bytes per k16 step
            uint32_t af[4][4];
#pragma unroll
            for (int i = 0; i < 4; ++i) ldsm4(af[i], st + a_off[i] + kbb);
            uint32_t bg[4][2], bu[4][2];
#pragma unroll
            for (int p = 0; p < 2; ++p) {
                uint32_t t[4];
                ldsm4(t, st + bg_off[0] + (uint32_t)(p * 16 * ROWW) * 4 + kbb);
                bg[2*p][0] = t[0]; bg[2*p][1] = t[1]; bg[2*p+1][0] = t[2]; bg[2*p+1][1] = t[3];
                ldsm4(t, st + bu_off[0] + (uint32_t)(p * 16 * ROWW) * 4 + kbb);
                bu[2*p][0] = t[0]; bu[2*p][1] = t[1]; bu[2*p+1][0] = t[2]; bu[2*p+1][1] = t[3];
            }
#pragma unroll
            for (int i = 0; i < 4; ++i)
#pragma unroll
                for (int j = 0; j < 4; ++j) {
                    mma16(accg[i][j], af[i], bg[j]);
                    mma16(accu[i][j], af[i], bu[j]);
                }
        }

        __syncthreads();
        if (kt + 2 < KT) load_stage(cur, kt + 2);
        CP_COMMIT();
    }

    // Epilogue: h = silu(g)*u stored as fp16 pairs (pad cols exactly 0).
#pragma unroll
    for (int i = 0; i < 4; ++i)
#pragma unroll
        for (int j = 0; j < 4; ++j) {
            int c0 = bn + wn + j * 8 + 2 * lc4;
#pragma unroll
            for (int half = 0; half < 2; ++half) {
                int r = bm + wm + i * 16 + lr4 + half * 8;
                float g0 = accg[i][j][half * 2], g1 = accg[i][j][half * 2 + 1];
                float u0 = accu[i][j][half * 2], u1 = accu[i][j][half * 2 + 1];
                float h0 = g0 * u0 / (1.0f + __expf(-g0));
                float h1 = g1 * u1 / (1.0f + __expf(-g1));
                g_hh[(size_t)r * HW_K + c0 / 2] = pack2(h0, h1);
            }
        }
}

// ---------------------------------------------------------------------------
// Kernel 2: out = h @ Wd_packed^T.
// CTA 256(M) x 128(N), K step 128 elems. 256 threads, 8 warps (4x2),
// warp tile 64x64, fp16 m16n8k16, ldmatrix.x4.
// Stage layout (words): A@0 (256x68), B@17408 (128x68).
// ---------------------------------------------------------------------------
__global__ __launch_bounds__(256, 1) void k_down(float* __restrict__ out) {
    extern __shared__ uint32_t sm[];
    const int tid = threadIdx.x;
    const uint32_t sbase = (uint32_t)__cvta_generic_to_shared(sm);

    int bid   = blockIdx.x;                     // 32 m-tiles x 32 n-tiles, GRP 8
    int group = bid / (8 * 32);
    int rem   = bid - group * (8 * 32);
    const int bm = (group * 8 + (rem & 7)) * 256;
    const int bn = (rem >> 3) * 128;

    auto load_stage = [&](int s, int kt) {
        const uint32_t base = sbase + (uint32_t)(s * STG_W) * 4;
        const int gk = kt * 64;
#pragma unroll
        for (int i = 0; i < 16; ++i) {
            int ch  = tid + 256 * i;
            int row = ch >> 4, c = (ch & 15) * 4;
            cp16(base + (uint32_t)(row * ROWW + c) * 4,
                 g_hh + (size_t)(bm + row) * HW_K + gk + c);
        }
#pragma unroll
        for (int i = 0; i < 8; ++i) {
            int ch  = tid + 256 * i;
            int row = ch >> 4, c = (ch & 15) * 4;
            cp16(base + 17408 * 4 + (uint32_t)(row * ROWW + c) * 4,
                 g_wdh + (size_t)(bn + row) * HW_K + gk + c);
        }
    };

    const int warp = tid >> 5, lane = tid & 31;
    const int wm = (warp & 3) * 64;
    const int wn = (warp >> 2) * 64;
    const int lr4 = lane >> 2, lc4 = lane & 3;

    uint32_t a_off[4];
#pragma unroll
    for (int i = 0; i < 4; ++i) {
        int row = wm + i * 16 + ((lane >> 3) & 1) * 8 + (lane & 7);
        a_off[i] = (uint32_t)(row * ROWW + ((lane >> 4) & 1) * 4) * 4;
    }
    uint32_t b_off0;
    {
        int row = wn + ((lane >> 4) & 1) * 8 + (lane & 7);
        b_off0 = 17408u * 4 + (uint32_t)(row * ROWW + ((lane >> 3) & 1) * 4) * 4;
    }

    float acc[4][8][4] = {};

    const int KT = KPAD / 128;                  // 26
    load_stage(0, 0); CP_COMMIT();
    load_stage(1, 1); CP_COMMIT();

    for (int kt = 0; kt < KT; ++kt) {
        const int cur = kt & 1;
        CP_WAIT1();
        __syncthreads();

        const uint32_t st = sbase + (uint32_t)(cur * STG_W) * 4;
#pragma unroll
        for (int kk = 0; kk < 8; ++kk) {
            const uint32_t kbb = kk * 32;
            uint32_t af[4][4];
#pragma unroll
            for (int i = 0; i < 4; ++i) ldsm4(af[i], st + a_off[i] + kbb);
            uint32_t bf[8][2];
#pragma unroll
            for (int p = 0; p < 4; ++p) {
                uint32_t t[4];
                ldsm4(t, st + b_off0 + (uint32_t)(p * 16 * ROWW) * 4 + kbb);
                bf[2*p][0] = t[0]; bf[2*p][1] = t[1]; bf[2*p+1][0] = t[2]; bf[2*p+1][1] = t[3];
            }
#pragma unroll
            for (int i = 0; i < 4; ++i)
#pragma unroll
                for (int j = 0; j < 8; ++j)
                    mma16(acc[i][j], af[i], bf[j]);
        }

        __syncthreads();
        if (kt + 2 < KT) load_stage(cur, kt + 2);
        CP_COMMIT();
    }

#pragma unroll
    for (int i = 0; i < 4; ++i)
#pragma unroll
        for (int j = 0; j < 8; ++j) {
            int c0 = bn + wn + j * 8 + 2 * lc4;
#pragma unroll
            for (int half = 0; half < 2; ++half) {
                int r = bm + wm + i * 16 + lr4 + half * 8;
                *(float2*)(out + (size_t)r * HIDDEN + c0) =
                    make_float2(acc[i][j][half * 2], acc[i][j][half * 2 + 1]);
            }
        }
}

// ---------------------------------------------------------------------------
// Inputs: x[f32 8192x4096], W_gate[f32 11008x4096], W_up[f32 11008x4096],
// W_down[f32 4096x11008], active_idx[i32 3302]. Output f32 8192x4096.
// ---------------------------------------------------------------------------
extern "C" void kernel_launch(void* const* d_in, const int* in_sizes, int n_in,
                              void* d_out, int out_size)
{
    const float* x    = (const float*)d_in[0];
    const float* Wg   = (const float*)d_in[1];
    const float* Wu   = (const float*)d_in[2];
    const float* Wd   = (const float*)d_in[3];
    const int*   aidx = (const int*)  d_in[4];
    float*       out  = (float*)d_out;

    cudaFuncSetAttribute(k_gateup, cudaFuncAttributeMaxDynamicSharedMemorySize, SMEM_B);
    cudaFuncSetAttribute(k_down,   cudaFuncAttributeMaxDynamicSharedMemorySize, SMEM_B);

    k_cvt_x  <<<(TOKENS * HIDDEN) / 1024, 256>>>(x);
    k_prep_gu<<<KPAD,   256>>>(Wg, Wu, aidx);
    k_prep_wd<<<HIDDEN, 256>>>(Wd, aidx);

    k_gateup<<<(TOKENS / 256) * (KPAD / 64),    256, SMEM_B>>>();     // 32*52 = 1664
    k_down  <<<(TOKENS / 256) * (HIDDEN / 128), 256, SMEM_B>>>(out);  // 32*32 = 1024
}